// round 8
// baseline (speedup 1.0000x reference)
#include <cuda_runtime.h>

#define NN 20000
#define NE 320000
#define SQRT3F 1.7320508075688772f
#define INV_NORM (1.0f/319999.0f)

typedef unsigned long long u64;

// ---------------- persistent device state (no allocs allowed) ----------------
__device__ __align__(16) float g_s[NN*16];      // node scalars
__device__ __align__(16) float g_v[NN*3];       // node vector (positions)
__device__ __align__(16) float g_accS[NN*16];   // aggregated scalar messages
__device__ __align__(16) float g_accV[NN*48];   // aggregated vector messages [16][3]
__device__ __align__(16) float g_accAv[NN*3];   // aggregated edge attr vectors
__device__ int g_cnt_i[NN];                     // per-receiver edge counts
__device__ int g_row[NN+1];                     // CSR row offsets (receiver-sorted)
__device__ int g_fill[NN];                      // scatter cursors
__device__ int g_src[NE];                       // senders in receiver-sorted order
__device__ int g_dst[NE];                       // receivers in receiver-sorted order
__device__ float g_msg[(size_t)67*NE];          // channel-major message buffer (~86MB)

// ---------------- f32x2 packed-math helpers (sm_103a dual FMA pipe) ----------
__device__ __forceinline__ u64 pk2(float a, float b){ u64 r; asm("mov.b64 %0,{%1,%2};":"=l"(r):"f"(a),"f"(b)); return r; }
__device__ __forceinline__ u64 bc2(float a){ return pk2(a,a); }
__device__ __forceinline__ void upk2(u64 v, float&a, float&b){ asm("mov.b64 {%0,%1},%2;":"=f"(a),"=f"(b):"l"(v)); }
__device__ __forceinline__ void fma2_(u64&d, u64 a, u64 b){ asm("fma.rn.f32x2 %0,%1,%2,%0;":"+l"(d):"l"(a),"l"(b)); }
__device__ __forceinline__ u64 mul2_(u64 a, u64 b){ u64 r; asm("mul.rn.f32x2 %0,%1,%2;":"=l"(r):"l"(a),"l"(b)); return r; }

__device__ __forceinline__ float sigmoidf_(float x){
    return 1.0f/(1.0f+__expf(-x));
}
// jax.nn.gelu default (approximate=True)
__device__ __forceinline__ float geluf_(float x){
    float t = 0.7978845608028654f*(x + 0.044715f*x*x*x);
    float e = __expf(2.0f*t);
    float th = 1.0f - 2.0f/(e+1.0f);
    return 0.5f*x*(1.0f+th);
}

// ---------------- init / CSR build / pack ----------------
__global__ void init_kernel(const float* __restrict__ s_in, const float* __restrict__ v_in){
    int i = blockIdx.x*256 + threadIdx.x;
    if (i < NN*16) g_s[i] = s_in[i];
    if (i < NN*3)  g_v[i] = v_in[i];
    if (i < NN)    g_cnt_i[i] = 0;
}

__global__ void count_kernel(const int* __restrict__ receivers){
    int e = blockIdx.x*256 + threadIdx.x;
    if (e < NE) atomicAdd(&g_cnt_i[receivers[e]], 1);
}

__global__ void scan_kernel(){
    __shared__ int part[1024];
    int t = threadIdx.x;
    int base = t*20;
    int s = 0;
    if (base < NN){
        #pragma unroll
        for (int i=0;i<20;i++){ int n=base+i; if (n<NN) s += g_cnt_i[n]; }
    }
    part[t]=s; __syncthreads();
    for (int off=1;off<1024;off<<=1){
        int v = (t>=off)?part[t-off]:0;
        __syncthreads();
        part[t]+=v;
        __syncthreads();
    }
    int excl = (t==0)?0:part[t-1];
    if (base < NN){
        int run = excl;
        #pragma unroll
        for (int i=0;i<20;i++){
            int n=base+i;
            if (n<NN){ g_row[n]=run; g_fill[n]=run; run+=g_cnt_i[n]; }
        }
    }
    if (t==1023) g_row[NN]=part[1023];
}

__global__ void scatter_kernel(const int* __restrict__ senders, const int* __restrict__ receivers){
    int e = blockIdx.x*256 + threadIdx.x;
    if (e >= NE) return;
    int ri = receivers[e];
    int s = atomicAdd(&g_fill[ri], 1);
    g_src[s] = senders[e];
    g_dst[s] = ri;
}

__global__ void pack_kernel(float* __restrict__ out){
    int n = blockIdx.x*256 + threadIdx.x;
    if (n >= NN) return;
    #pragma unroll
    for (int p=0;p<16;p++) out[n*19+p] = g_s[n*16+p];
    out[n*19+16] = g_v[n*3+0];
    out[n*19+17] = g_v[n*3+1];
    out[n*19+18] = g_v[n*3+2];
}

// ---------------- edge kernel: 2 edges per thread (weight LDS amortized 2x) ----------------
__global__ void __launch_bounds__(128) edge_kernel(
    const float* __restrict__ Ws0, const float* __restrict__ bs0, const float* __restrict__ Wv0,
    const float* __restrict__ Ws1, const float* __restrict__ bs1, const float* __restrict__ Wv1)
{
    __shared__ __align__(16) float sWs0[34*32];
    __shared__ __align__(16) float sWv0[34*16];
    __shared__ __align__(16) float sWs1[32*32];
    __shared__ __align__(16) float sWv1[32*16];
    __shared__ __align__(16) float sbs0[32];
    __shared__ __align__(16) float sbs1[32];
    int tid = threadIdx.x;
    for (int i=tid;i<34*32;i+=128) sWs0[i]=Ws0[i];
    for (int i=tid;i<34*16;i+=128) sWv0[i]=Wv0[i];
    for (int i=tid;i<32*32;i+=128) sWs1[i]=Ws1[i];
    for (int i=tid;i<32*16;i+=128) sWv1[i]=Wv1[i];
    if (tid<32){ sbs0[tid]=bs0[tid]; sbs1[tid]=bs1[tid]; }
    __syncthreads();

    int s0 = (blockIdx.x*128 + tid)*2;       // this thread owns slots s0, s0+1
    if (s0 >= NE) return;                     // NE even -> both slots valid
    int siA = g_src[s0],   riA = g_dst[s0];
    int siB = g_src[s0+1], riB = g_dst[s0+1];

    // geometry, edge A
    float vsxA=g_v[siA*3+0], vsyA=g_v[siA*3+1], vszA=g_v[siA*3+2];
    float vrxA=g_v[riA*3+0], vryA=g_v[riA*3+1], vrzA=g_v[riA*3+2];
    float rxA=vsxA-vrxA, ryA=vsyA-vryA, rzA=vszA-vrzA;
    float kkA = SQRT3F/(sqrtf(rxA*rxA+ryA*ryA+rzA*rzA)+1e-8f);
    float avxA=kkA*rxA, avyA=kkA*ryA, avzA=kkA*rzA;
    // geometry, edge B
    float vsxB=g_v[siB*3+0], vsyB=g_v[siB*3+1], vszB=g_v[siB*3+2];
    float vrxB=g_v[riB*3+0], vryB=g_v[riB*3+1], vrzB=g_v[riB*3+2];
    float rxB=vsxB-vrxB, ryB=vsyB-vryB, rzB=vszB-vrzB;
    float kkB = SQRT3F/(sqrtf(rxB*rxB+ryB*ryB+rzB*rzB)+1e-8f);
    float avxB=kkB*rxB, avyB=kkB*ryB, avzB=kkB*rzB;

    float xsA[32], xsB[32];
    {
        const float4* a0 = (const float4*)(g_s + siA*16);
        const float4* a1 = (const float4*)(g_s + riA*16);
        const float4* b0p = (const float4*)(g_s + siB*16);
        const float4* b1p = (const float4*)(g_s + riB*16);
        #pragma unroll
        for (int j=0;j<4;j++){ float4 t=a0[j]; xsA[4*j]=t.x; xsA[4*j+1]=t.y; xsA[4*j+2]=t.z; xsA[4*j+3]=t.w; }
        #pragma unroll
        for (int j=0;j<4;j++){ float4 t=a1[j]; xsA[16+4*j]=t.x; xsA[16+4*j+1]=t.y; xsA[16+4*j+2]=t.z; xsA[16+4*j+3]=t.w; }
        #pragma unroll
        for (int j=0;j<4;j++){ float4 t=b0p[j]; xsB[4*j]=t.x; xsB[4*j+1]=t.y; xsB[4*j+2]=t.z; xsB[4*j+3]=t.w; }
        #pragma unroll
        for (int j=0;j<4;j++){ float4 t=b1p[j]; xsB[16+4*j]=t.x; xsB[16+4*j+1]=t.y; xsB[16+4*j+2]=t.z; xsB[16+4*j+3]=t.w; }
    }
    float dSA = vsxA*avxA+vsyA*avyA+vszA*avzA;
    float dRA = vrxA*avxA+vryA*avyA+vrzA*avzA;
    float dSB = vsxB*avxB+vsyB*avyB+vszB*avzB;
    float dRB = vrxB*avxB+vryB*avyB+vrzB*avzB;

    // ---- layer 1: shared weight loads feed both edges ----
    u64 slA[16], slB[16], uA[8], uB[8];
    {
        u64 dSA2=bc2(dSA), dRA2=bc2(dRA), dSB2=bc2(dSB), dRB2=bc2(dRB);
        const u64* b0  = (const u64*)sbs0;
        const u64* w32 = (const u64*)(sWs0 + 32*32);
        const u64* w33 = (const u64*)(sWs0 + 33*32);
        #pragma unroll
        for (int k=0;k<16;k++){
            u64 bb=b0[k], wa=w32[k], wb=w33[k];
            slA[k]=bb; fma2_(slA[k],dSA2,wa); fma2_(slA[k],dRA2,wb);
            slB[k]=bb; fma2_(slB[k],dSB2,wa); fma2_(slB[k],dRB2,wb);
        }
        #pragma unroll
        for (int k=0;k<8;k++){ uA[k]=0ull; uB[k]=0ull; }
    }
    #pragma unroll 4
    for (int a=0;a<32;a++){
        u64 xaA = bc2(xsA[a]), xaB = bc2(xsB[a]);
        const u64* w = (const u64*)(sWs0 + a*32);
        #pragma unroll
        for (int k=0;k<16;k++){ u64 ww=w[k]; fma2_(slA[k],xaA,ww); fma2_(slB[k],xaB,ww); }
        const u64* v = (const u64*)(sWv0 + a*16);
        #pragma unroll
        for (int k=0;k<8;k++){ u64 vv=v[k]; fma2_(uA[k],xaA,vv); fma2_(uB[k],xaB,vv); }
    }

    float slAf[32], slBf[32], uAf[16], uBf[16];
    #pragma unroll
    for (int k=0;k<16;k++){ upk2(slA[k], slAf[2*k], slAf[2*k+1]); upk2(slB[k], slBf[2*k], slBf[2*k+1]); }
    #pragma unroll
    for (int k=0;k<8;k++){ upk2(uA[k], uAf[2*k], uAf[2*k+1]); upk2(uB[k], uBf[2*k], uBf[2*k+1]); }

    float msA[16], mvxA[16], mvyA[16], mvzA[16];
    float msB[16], mvxB[16], mvyB[16], mvzB[16];
    #pragma unroll
    for (int q=0;q<16;q++){
        float w32q = sWv0[32*16+q], w33q = sWv0[33*16+q];
        float gA = sigmoidf_(slAf[q]);
        mvxA[q] = (avxA*uAf[q] + vsxA*w32q + vrxA*w33q)*gA;
        mvyA[q] = (avyA*uAf[q] + vsyA*w32q + vryA*w33q)*gA;
        mvzA[q] = (avzA*uAf[q] + vszA*w32q + vrzA*w33q)*gA;
        msA[q]  = geluf_(slAf[16+q]);
        float gB = sigmoidf_(slBf[q]);
        mvxB[q] = (avxB*uBf[q] + vsxB*w32q + vrxB*w33q)*gB;
        mvyB[q] = (avyB*uBf[q] + vsyB*w32q + vryB*w33q)*gB;
        mvzB[q] = (avzB*uBf[q] + vszB*w32q + vrzB*w33q)*gB;
        msB[q]  = geluf_(slBf[16+q]);
    }

    // ---- layer 2: shared weight loads ----
    u64 s2A[16], s2B[16], u2A[8], u2B[8];
    {
        const u64* b1 = (const u64*)sbs1;
        #pragma unroll
        for (int k=0;k<16;k++){ s2A[k]=b1[k]; s2B[k]=b1[k]; }
        #pragma unroll
        for (int k=0;k<8;k++){ u2A[k]=0ull; u2B[k]=0ull; }
    }
    #pragma unroll 2
    for (int p=0;p<16;p++){
        float d2A = mvxA[p]*avxA + mvyA[p]*avyA + mvzA[p]*avzA;
        float d2B = mvxB[p]*avxB + mvyB[p]*avyB + mvzB[p]*avzB;
        u64 mA=bc2(msA[p]), mB=bc2(msB[p]), dA=bc2(d2A), dB=bc2(d2B);
        const u64* w  = (const u64*)(sWs1 + p*32);
        const u64* wb = (const u64*)(sWs1 + (16+p)*32);
        #pragma unroll
        for (int k=0;k<16;k++){
            u64 w1=w[k], w2=wb[k];
            fma2_(s2A[k],mA,w1); fma2_(s2A[k],dA,w2);
            fma2_(s2B[k],mB,w1); fma2_(s2B[k],dB,w2);
        }
        const u64* v = (const u64*)(sWv1 + p*16);
        #pragma unroll
        for (int k=0;k<8;k++){ u64 vv=v[k]; fma2_(u2A[k],mA,vv); fma2_(u2B[k],mB,vv); }
    }

    // unpack layer2 scalars; write scalar messages (channels 0..15) as float2, keep gates
    float gAv[16], gBv[16];
    {
        #pragma unroll
        for (int k=0;k<8;k++){
            float a0,a1,b0f,b1f;
            upk2(s2A[k],a0,a1); upk2(s2B[k],b0f,b1f);
            gAv[2*k]=sigmoidf_(a0); gAv[2*k+1]=sigmoidf_(a1);
            gBv[2*k]=sigmoidf_(b0f); gBv[2*k+1]=sigmoidf_(b1f);
        }
        #pragma unroll
        for (int k=0;k<8;k++){
            float a0,a1,b0f,b1f;
            upk2(s2A[8+k],a0,a1); upk2(s2B[8+k],b0f,b1f);
            float2 m0; m0.x=geluf_(a0); m0.y=geluf_(b0f);
            float2 m1; m1.x=geluf_(a1); m1.y=geluf_(b1f);
            *(float2*)(g_msg + (size_t)(2*k)*NE   + s0) = m0;
            *(float2*)(g_msg + (size_t)(2*k+1)*NE + s0) = m1;
        }
    }
    // edge-attr channels 64..66
    { float2 t; t.x=avxA; t.y=avxB; *(float2*)(g_msg + (size_t)64*NE + s0)=t; }
    { float2 t; t.x=avyA; t.y=avyB; *(float2*)(g_msg + (size_t)65*NE + s0)=t; }
    { float2 t; t.x=avzA; t.y=avzB; *(float2*)(g_msg + (size_t)66*NE + s0)=t; }

    // ---- vector output, chunked over q (2 chunks of 8 channels) ----
    u64 axA2=bc2(avxA), ayA2=bc2(avyA), azA2=bc2(avzA);
    u64 axB2=bc2(avxB), ayB2=bc2(avyB), azB2=bc2(avzB);
    #pragma unroll 1
    for (int c=0;c<2;c++){
        u64 vxA[4], vyA[4], vzA[4], vxB[4], vyB[4], vzB[4];
        #pragma unroll
        for (int k=0;k<4;k++){
            vxA[k]=mul2_(axA2,u2A[4*c+k]); vyA[k]=mul2_(ayA2,u2A[4*c+k]); vzA[k]=mul2_(azA2,u2A[4*c+k]);
            vxB[k]=mul2_(axB2,u2B[4*c+k]); vyB[k]=mul2_(ayB2,u2B[4*c+k]); vzB[k]=mul2_(azB2,u2B[4*c+k]);
        }
        #pragma unroll 4
        for (int p=0;p<16;p++){
            u64 mxA=bc2(mvxA[p]), myA=bc2(mvyA[p]), mzA=bc2(mvzA[p]);
            u64 mxB=bc2(mvxB[p]), myB=bc2(mvyB[p]), mzB=bc2(mvzB[p]);
            const u64* w2 = (const u64*)(sWv1 + (16+p)*16 + 8*c);
            #pragma unroll
            for (int k=0;k<4;k++){
                u64 ww=w2[k];
                fma2_(vxA[k],mxA,ww); fma2_(vyA[k],myA,ww); fma2_(vzA[k],mzA,ww);
                fma2_(vxB[k],mxB,ww); fma2_(vyB[k],myB,ww); fma2_(vzB[k],mzB,ww);
            }
        }
        #pragma unroll
        for (int k=0;k<4;k++){
            int q0 = 8*c + 2*k, q1 = q0+1;
            float x0A,x1A,y0A,y1A,z0A,z1A, x0B,x1B,y0B,y1B,z0B,z1B;
            upk2(vxA[k],x0A,x1A); upk2(vyA[k],y0A,y1A); upk2(vzA[k],z0A,z1A);
            upk2(vxB[k],x0B,x1B); upk2(vyB[k],y0B,y1B); upk2(vzB[k],z0B,z1B);
            float gA0=gAv[q0], gB0=gBv[q0], gA1=gAv[q1], gB1=gBv[q1];
            float2 t;
            t.x=x0A*gA0; t.y=x0B*gB0; *(float2*)(g_msg + (size_t)(16+3*q0+0)*NE + s0)=t;
            t.x=y0A*gA0; t.y=y0B*gB0; *(float2*)(g_msg + (size_t)(16+3*q0+1)*NE + s0)=t;
            t.x=z0A*gA0; t.y=z0B*gB0; *(float2*)(g_msg + (size_t)(16+3*q0+2)*NE + s0)=t;
            t.x=x1A*gA1; t.y=x1B*gB1; *(float2*)(g_msg + (size_t)(16+3*q1+0)*NE + s0)=t;
            t.x=y1A*gA1; t.y=y1B*gB1; *(float2*)(g_msg + (size_t)(16+3*q1+1)*NE + s0)=t;
            t.x=z1A*gA1; t.y=z1B*gB1; *(float2*)(g_msg + (size_t)(16+3*q1+2)*NE + s0)=t;
        }
    }
}

// ---------------- aggregation: contiguous per-node sums, fully coalesced ----------------
__global__ void __launch_bounds__(256) agg_kernel(){
    int n = blockIdx.x*256 + threadIdx.x;
    int c = blockIdx.y;
    if (n >= NN) return;
    int a = g_row[n], b = g_row[n+1];
    const float* p = g_msg + (size_t)c*NE;
    float sum = 0.f;
    for (int i=a;i<b;i++) sum += p[i];
    if (c < 16)      g_accS[n*16+c]      = sum;
    else if (c < 64) g_accV[n*48+(c-16)] = sum;
    else             g_accAv[n*3+(c-64)] = sum;
}

// ---------------- node kernel: thread-pair per node, channel-split ----------------
__global__ void __launch_bounds__(256) node_kernel(
    const float* __restrict__ nWs, const float* __restrict__ nbs, const float* __restrict__ nWv,
    const float* __restrict__ fWs, const float* __restrict__ fbs, const float* __restrict__ fWv)
{
    __shared__ __align__(16) float sW[2*289*18];
    __shared__ __align__(16) float sV[2*289];
    __shared__ __align__(16) float sB[2*17];
    __shared__ __align__(16) float sF[256];
    __shared__ __align__(16) float sFb[16];
    __shared__ float sFv[1];
    int tid = threadIdx.x;
    for (int i=tid;i<2*289*17;i+=256){
        int b = i/(289*17); int r = i - b*289*17; int p = r/17; int q = r - p*17;
        sW[b*289*18 + p*18 + q] = nWs[i];
    }
    for (int i=tid;i<2*289;i+=256) sV[i]=nWv[i];
    if (tid<34) sB[tid]=nbs[tid];
    if (tid<256) sF[tid]=fWs[tid];
    if (tid<16) sFb[tid]=fbs[tid];
    if (tid==0) sFv[0]=fWv[0];
    __syncthreads();

    int id = blockIdx.x*256 + tid;
    bool valid = (id < 2*NN);
    int n  = valid ? (id >> 1) : (NN-1);   // clamp: ghost threads compute but never store
    int h  = id & 1;

    int r0i = g_row[n], r1i = g_row[n+1];
    float cnt = (float)(r1i - r0i);
    float fsc = INV_NORM / fmaxf(cnt,1.0f);
    float ys[17];
    #pragma unroll
    for (int c=0;c<16;c++) ys[c] = g_accS[n*16+c]*fsc;
    ys[16] = (cnt>0.f) ? INV_NORM : 0.f;

    float nsv[16];
    #pragma unroll
    for (int a=0;a<16;a++) nsv[a]=g_s[n*16+a];
    float nvx=g_v[n*3+0], nvy=g_v[n*3+1], nvz=g_v[n*3+2];

    int hoff = 8*h;

    #pragma unroll 1
    for (int b=0;b<2;b++){
        const float* Wb = sW + b*289*18;
        const float* Vb = sV + b*289;
        u64 sl2[4];
        float sl16;
        {
            #pragma unroll
            for (int k=0;k<4;k++) sl2[k]=pk2(sB[b*17+hoff+2*k], sB[b*17+hoff+2*k+1]);
            sl16 = sB[b*17+16];
        }
        float wv[17];
        #pragma unroll
        for (int d=0;d<17;d++) wv[d]=0.f;

        for (int a=0;a<16;a++){
            float na = nsv[a];
            #pragma unroll
            for (int c=0;c<17;c++){
                float t = na*ys[c];
                u64 t2 = bc2(t);
                const u64* wr = (const u64*)(Wb + (a*17+c)*18 + hoff);
                #pragma unroll
                for (int k=0;k<4;k++) fma2_(sl2[k], t2, wr[k]);
                sl16  += t*Wb[(a*17+c)*18+16];
                wv[c] += na*Vb[a*17+c];
            }
        }

        float vx=0.f, vy=0.f, vz=0.f;
        #pragma unroll
        for (int d=0;d<17;d++){
            float yx,yy,yz;
            if (d<16){ yx=g_accV[n*48+d*3+0]*fsc; yy=g_accV[n*48+d*3+1]*fsc; yz=g_accV[n*48+d*3+2]*fsc; }
            else     { yx=g_accAv[n*3+0]*fsc;     yy=g_accAv[n*3+1]*fsc;     yz=g_accAv[n*3+2]*fsc; }
            float t = nvx*yx+nvy*yy+nvz*yz;
            u64 t2 = bc2(t);
            const u64* wr = (const u64*)(Wb + (272+d)*18 + hoff);
            #pragma unroll
            for (int k=0;k<4;k++) fma2_(sl2[k], t2, wr[k]);
            sl16 += t*Wb[(272+d)*18+16];
            vx += yx*wv[d]; vy += yy*wv[d]; vz += yz*wv[d];
        }
        float sc=0.f;
        #pragma unroll
        for (int c=0;c<17;c++) sc += ys[c]*Vb[272+c];
        vx += nvx*sc; vy += nvy*sc; vz += nvz*sc;

        float slh[8];
        #pragma unroll
        for (int k=0;k<4;k++) upk2(sl2[k], slh[2*k], slh[2*k+1]);

        float ex[9];
        if (h==0){
            ex[0] = sigmoidf_(slh[0]);
            #pragma unroll
            for (int k=1;k<8;k++) ex[k] = geluf_(slh[k]);
            ex[8] = 0.f;
        } else {
            #pragma unroll
            for (int k=0;k<8;k++) ex[k] = geluf_(slh[k]);
            ex[8] = geluf_(sl16);
        }
        float ot[9];
        #pragma unroll
        for (int k=0;k<9;k++) ot[k] = __shfl_xor_sync(0xffffffffu, ex[k], 1);

        float g;
        if (h==0){
            g = ex[0];
            #pragma unroll
            for (int k=0;k<7;k++) nsv[k]   = ex[k+1];
            #pragma unroll
            for (int k=0;k<8;k++) nsv[7+k] = ot[k];
            nsv[15] = ot[8];
        } else {
            g = ot[0];
            #pragma unroll
            for (int k=0;k<7;k++) nsv[k]   = ot[k+1];
            #pragma unroll
            for (int k=0;k<8;k++) nsv[7+k] = ex[k];
            nsv[15] = ex[8];
        }
        nvx = vx*g; nvy = vy*g; nvz = vz*g;
    }

    u64 out2[4];
    {
        const u64* gs2 = (const u64*)(g_s + n*16 + hoff);
        const u64* fb2 = (const u64*)(sFb + hoff);
        #pragma unroll
        for (int k=0;k<4;k++){ out2[k]=gs2[k]; fma2_(out2[k], bc2(1.0f), fb2[k]); }
    }
    #pragma unroll
    for (int a=0;a<16;a++){
        u64 na2 = bc2(nsv[a]);
        const u64* w2 = (const u64*)(sF + a*16 + hoff);
        #pragma unroll
        for (int k=0;k<4;k++) fma2_(out2[k], na2, w2[k]);
    }
    if (valid){
        u64* gs2w = (u64*)(g_s + n*16 + hoff);
        #pragma unroll
        for (int k=0;k<4;k++) gs2w[k]=out2[k];
        if (h==0){
            float fv = sFv[0];
            g_v[n*3+0] += nvx*fv;
            g_v[n*3+1] += nvy*fv;
            g_v[n*3+2] += nvz*fv;
        }
    }
}

// ---------------- launch ----------------
extern "C" void kernel_launch(void* const* d_in, const int* in_sizes, int n_in,
                              void* d_out, int out_size)
{
    const float* node_s   = (const float*)d_in[0];
    const float* node_p   = (const float*)d_in[1];
    const int*   senders  = (const int*)d_in[2];
    const int*   receivers= (const int*)d_in[3];
    const float* eWs0 = (const float*)d_in[4];
    const float* ebs0 = (const float*)d_in[5];
    const float* eWv0 = (const float*)d_in[6];
    const float* eWs1 = (const float*)d_in[7];
    const float* ebs1 = (const float*)d_in[8];
    const float* eWv1 = (const float*)d_in[9];
    const float* nWs  = (const float*)d_in[10];
    const float* nbs  = (const float*)d_in[11];
    const float* nWv  = (const float*)d_in[12];
    const float* fWs  = (const float*)d_in[13];
    const float* fbs  = (const float*)d_in[14];
    const float* fWv  = (const float*)d_in[15];

    init_kernel<<<(NN*16+255)/256,256>>>(node_s, node_p);
    count_kernel<<<(NE+255)/256,256>>>(receivers);
    scan_kernel<<<1,1024>>>();
    scatter_kernel<<<(NE+255)/256,256>>>(senders, receivers);

    for (int t=0;t<3;t++){
        edge_kernel<<<(NE/2+127)/128,128>>>(
            eWs0 + t*34*32, ebs0 + t*32, eWv0 + t*34*16,
            eWs1 + t*32*32, ebs1 + t*32, eWv1 + t*32*16);
        agg_kernel<<<dim3((NN+255)/256, 67),256>>>();
        node_kernel<<<(2*NN+255)/256,256>>>(
            nWs + t*2*289*17, nbs + t*2*17, nWv + t*2*289,
            fWs + t*256, fbs + t*16, fWv + t);
    }
    pack_kernel<<<(NN+255)/256,256>>>((float*)d_out);
}